// round 3
// baseline (speedup 1.0000x reference)
#include <cuda_runtime.h>
#include <math.h>

#define HKD  128
#define NKH  16
#define NVH  32
#define QKVD 8192

__device__ __forceinline__ float wredu(float v) {
#pragma unroll
    for (int o = 16; o; o >>= 1) v += __shfl_xor_sync(0xffffffffu, v, o);
    return v;
}

__device__ __forceinline__ float dot4(float4 a, float4 b) {
    return a.x * b.x + a.y * b.y + a.z * b.z + a.w * b.w;
}

__global__ __launch_bounds__(128) void gdn_decode_kernel(
    const float* __restrict__ mixed_qkv,
    const float* __restrict__ bgate,
    const float* __restrict__ agate,
    const float* __restrict__ conv_state,
    const float* __restrict__ conv_w,
    const float* __restrict__ ssm,
    const float* __restrict__ alog,
    const float* __restrict__ dt_bias,
    float* __restrict__ out)
{
    const int bh = blockIdx.x;
    const int b  = bh >> 5;
    const int h  = bh & 31;
    const int hq = h >> 1;                 // GROUP = 2
    const int t    = threadIdx.x;
    const int lane = t & 31;
    const int wid  = t >> 5;

    __shared__ __align__(16) float q_s[HKD];
    __shared__ __align__(16) float k_s[HKD];
    __shared__ __align__(16) float v_s[HKD];
    __shared__ float red[12];

    // ---- prefetch batch 0 of state rows BEFORE any prologue work ----
    const float4* Sb = (const float4*)(ssm + (size_t)bh * HKD * HKD)
                       + (size_t)wid * 32 * 32 + lane;
    float4 c0 = __ldcs(Sb + 0 * 32);
    float4 c1 = __ldcs(Sb + 1 * 32);
    float4 c2 = __ldcs(Sb + 2 * 32);
    float4 c3 = __ldcs(Sb + 3 * 32);

    // ---- causal conv (4 taps) + SiLU for this CTA's q/k/v channels ----
    const float* cs = conv_state + (size_t)b * 3 * QKVD;
    const float* mq = mixed_qkv  + (size_t)b * QKVD;
    const int cq = hq * HKD + t;
    const int ck = NKH * HKD + hq * HKD + t;
    const int cv = 2 * NKH * HKD + h * HKD + t;

    float qx, kx, vx;
    {
        float4 w = *(const float4*)(conv_w + (size_t)cq * 4);
        float x  = cs[cq] * w.x + cs[QKVD + cq] * w.y + cs[2 * QKVD + cq] * w.z + mq[cq] * w.w;
        qx = x / (1.f + expf(-x));

        w = *(const float4*)(conv_w + (size_t)ck * 4);
        x = cs[ck] * w.x + cs[QKVD + ck] * w.y + cs[2 * QKVD + ck] * w.z + mq[ck] * w.w;
        kx = x / (1.f + expf(-x));

        w = *(const float4*)(conv_w + (size_t)cv * 4);
        x = cs[cv] * w.x + cs[QKVD + cv] * w.y + cs[2 * QKVD + cv] * w.z + mq[cv] * w.w;
        vx = x / (1.f + expf(-x));
    }

    // raw values to shared, single fused reduction (q^2, k^2, q.k)
    q_s[t] = qx;
    k_s[t] = kx;
    v_s[t] = vx;
    float pq = wredu(qx * qx);
    float pk = wredu(kx * kx);
    float pc = wredu(qx * kx);
    if (lane == 0) { red[wid] = pq; red[4 + wid] = pk; red[8 + wid] = pc; }

    // ---- gating scalars (independent of the reduction; hides sync) ----
    const float aa   = agate[(size_t)b * NVH + h] + dt_bias[h];
    const float sp   = fmaxf(aa, 0.f) + log1pf(expf(-fabsf(aa)));   // softplus
    const float eg   = expf(-expf(alog[h]) * sp);                   // exp(g)
    const float beta = 1.f / (1.f + expf(-bgate[(size_t)b * NVH + h]));

    __syncthreads();   // the only barrier

    const float rq = rsqrtf(red[0] + red[1] + red[2] + red[3] + 1e-6f)
                     * 0.08838834764831845f;                        // * HK^-0.5
    const float rk = rsqrtf(red[4] + red[5] + red[6] + red[7] + 1e-6f);
    const float kq = (red[8] + red[9] + red[10] + red[11]) * rq * rk;

    float4 q4 = ((const float4*)q_s)[lane];
    q4.x *= rq; q4.y *= rq; q4.z *= rq; q4.w *= rq;
    float4 k4 = ((const float4*)k_s)[lane];
    k4.x *= rk; k4.y *= rk; k4.z *= rk; k4.w *= rk;

    float*       op = out + (size_t)bh * HKD + wid * 32;
    const float* vr = v_s + wid * 32;

    // This lane finishes holding one of the 8 batch sums, selected by lane
    // bits {4,3,2}: bit4 -> dq vs dk, r = bit3 + 2*bit2. Lanes 16,20,24,28
    // (one per row) write the outputs.
    const bool s4 = (lane & 16) != 0;
    const bool s3 = (lane & 8)  != 0;
    const bool s2 = (lane & 4)  != 0;
    const bool writer = ((lane & 19) == 16);   // bit4 set, bits 0..1 clear
    const int  rsel   = ((lane >> 3) & 1) | (((lane >> 2) & 1) << 1);

    // ---- 8 batches of 4 rows, double-buffered; merged 8-way reduction ----
#pragma unroll
    for (int j = 0; j < 8; j++) {
        float4 n0 = {}, n1 = {}, n2 = {}, n3 = {};
        if (j < 7) {
            n0 = __ldcs(Sb + ((j + 1) * 4 + 0) * 32);
            n1 = __ldcs(Sb + ((j + 1) * 4 + 1) * 32);
            n2 = __ldcs(Sb + ((j + 1) * 4 + 2) * 32);
            n3 = __ldcs(Sb + ((j + 1) * 4 + 3) * 32);
        }

        // a[2r] = dk_r, a[2r+1] = dq_r
        float a0 = dot4(c0, k4), a1 = dot4(c0, q4);
        float a2 = dot4(c1, k4), a3 = dot4(c1, q4);
        float a4 = dot4(c2, k4), a5 = dot4(c2, q4);
        float a6 = dot4(c3, k4), a7 = dot4(c3, q4);

        // level 16 (8 shfl), merge on bit4
        a0 += __shfl_xor_sync(0xffffffffu, a0, 16);
        a1 += __shfl_xor_sync(0xffffffffu, a1, 16);
        a2 += __shfl_xor_sync(0xffffffffu, a2, 16);
        a3 += __shfl_xor_sync(0xffffffffu, a3, 16);
        a4 += __shfl_xor_sync(0xffffffffu, a4, 16);
        a5 += __shfl_xor_sync(0xffffffffu, a5, 16);
        a6 += __shfl_xor_sync(0xffffffffu, a6, 16);
        a7 += __shfl_xor_sync(0xffffffffu, a7, 16);
        float b0 = s4 ? a1 : a0;
        float b1 = s4 ? a3 : a2;
        float b2 = s4 ? a5 : a4;
        float b3 = s4 ? a7 : a6;

        // level 8 (4 shfl), merge on bit3
        b0 += __shfl_xor_sync(0xffffffffu, b0, 8);
        b1 += __shfl_xor_sync(0xffffffffu, b1, 8);
        b2 += __shfl_xor_sync(0xffffffffu, b2, 8);
        b3 += __shfl_xor_sync(0xffffffffu, b3, 8);
        float e0 = s3 ? b1 : b0;
        float e1 = s3 ? b3 : b2;

        // level 4 (2 shfl), merge on bit2
        e0 += __shfl_xor_sync(0xffffffffu, e0, 4);
        e1 += __shfl_xor_sync(0xffffffffu, e1, 4);
        float dsum = s2 ? e1 : e0;

        // levels 2, 1
        dsum += __shfl_xor_sync(0xffffffffu, dsum, 2);
        dsum += __shfl_xor_sync(0xffffffffu, dsum, 1);

        // pair dq (bit4 lanes) with dk (partner lane)
        float dk = __shfl_xor_sync(0xffffffffu, dsum, 16);

        if (writer) {
            const int r = j * 4 + rsel;
            op[r] = eg * dsum + beta * (vr[r] - eg * dk) * kq;
        }

        c0 = n0; c1 = n1; c2 = n2; c3 = n3;
    }
}

extern "C" void kernel_launch(void* const* d_in, const int* in_sizes, int n_in,
                              void* d_out, int out_size)
{
    const float* mixed_qkv  = (const float*)d_in[0];
    const float* bgate      = (const float*)d_in[1];
    const float* agate      = (const float*)d_in[2];
    const float* conv_state = (const float*)d_in[3];
    const float* conv_w     = (const float*)d_in[4];
    const float* ssm        = (const float*)d_in[5];
    const float* alog       = (const float*)d_in[6];
    const float* dt_bias    = (const float*)d_in[7];
    float* out = (float*)d_out;

    const int B = in_sizes[0] / QKVD;
    gdn_decode_kernel<<<B * NVH, 128>>>(mixed_qkv, bgate, agate, conv_state,
                                        conv_w, ssm, alog, dt_bias, out);
}

// round 4
// speedup vs baseline: 1.0194x; 1.0194x over previous
#include <cuda_runtime.h>
#include <math.h>

#define HKD  128
#define NKH  16
#define NVH  32
#define QKVD 8192

__device__ __forceinline__ float wredu(float v) {
#pragma unroll
    for (int o = 16; o; o >>= 1) v += __shfl_xor_sync(0xffffffffu, v, o);
    return v;
}

__device__ __forceinline__ float dot4(float4 a, float4 b) {
    return a.x * b.x + a.y * b.y + a.z * b.z + a.w * b.w;
}

__global__ __launch_bounds__(128) void gdn_decode_kernel(
    const float* __restrict__ mixed_qkv,
    const float* __restrict__ bgate,
    const float* __restrict__ agate,
    const float* __restrict__ conv_state,
    const float* __restrict__ conv_w,
    const float* __restrict__ ssm,
    const float* __restrict__ alog,
    const float* __restrict__ dt_bias,
    float* __restrict__ out)
{
    const int bh = blockIdx.x;
    const int b  = bh >> 5;
    const int h  = bh & 31;
    const int hq = h >> 1;                 // GROUP = 2
    const int t    = threadIdx.x;
    const int lane = t & 31;
    const int wid  = t >> 5;

    __shared__ __align__(16) float q_s[HKD];
    __shared__ __align__(16) float k_s[HKD];
    __shared__ __align__(16) float v_s[HKD];
    __shared__ float red[12];

    // ---- prefetch batches 0 and 1 (8 rows) BEFORE any prologue work:
    //      8 loads in flight per warp while the conv loads resolve ----
    const float4* Sb = (const float4*)(ssm + (size_t)bh * HKD * HKD)
                       + (size_t)wid * 32 * 32 + lane;
    float4 buf[2][4];
#pragma unroll
    for (int i = 0; i < 4; i++) buf[0][i] = __ldcs(Sb + i * 32);
#pragma unroll
    for (int i = 0; i < 4; i++) buf[1][i] = __ldcs(Sb + (4 + i) * 32);

    // ---- causal conv (4 taps) + SiLU for this CTA's q/k/v channels ----
    const float* cs = conv_state + (size_t)b * 3 * QKVD;
    const float* mq = mixed_qkv  + (size_t)b * QKVD;
    const int cq = hq * HKD + t;
    const int ck = NKH * HKD + hq * HKD + t;
    const int cv = 2 * NKH * HKD + h * HKD + t;

    float qx, kx, vx;
    {
        float4 w = *(const float4*)(conv_w + (size_t)cq * 4);
        float x  = cs[cq] * w.x + cs[QKVD + cq] * w.y + cs[2 * QKVD + cq] * w.z + mq[cq] * w.w;
        qx = x / (1.f + expf(-x));

        w = *(const float4*)(conv_w + (size_t)ck * 4);
        x = cs[ck] * w.x + cs[QKVD + ck] * w.y + cs[2 * QKVD + ck] * w.z + mq[ck] * w.w;
        kx = x / (1.f + expf(-x));

        w = *(const float4*)(conv_w + (size_t)cv * 4);
        x = cs[cv] * w.x + cs[QKVD + cv] * w.y + cs[2 * QKVD + cv] * w.z + mq[cv] * w.w;
        vx = x / (1.f + expf(-x));
    }

    // raw values to shared, single fused reduction (q^2, k^2, q.k)
    q_s[t] = qx;
    k_s[t] = kx;
    v_s[t] = vx;
    float pq = wredu(qx * qx);
    float pk = wredu(kx * kx);
    float pc = wredu(qx * kx);
    if (lane == 0) { red[wid] = pq; red[4 + wid] = pk; red[8 + wid] = pc; }

    // ---- gating scalars (independent of the reduction; hides sync) ----
    const float aa   = agate[(size_t)b * NVH + h] + dt_bias[h];
    const float sp   = fmaxf(aa, 0.f) + log1pf(expf(-fabsf(aa)));   // softplus
    const float eg   = expf(-expf(alog[h]) * sp);                   // exp(g)
    const float beta = 1.f / (1.f + expf(-bgate[(size_t)b * NVH + h]));

    __syncthreads();   // the only barrier

    const float rq = rsqrtf(red[0] + red[1] + red[2] + red[3] + 1e-6f)
                     * 0.08838834764831845f;                        // * HK^-0.5
    const float rk = rsqrtf(red[4] + red[5] + red[6] + red[7] + 1e-6f);
    const float kq = (red[8] + red[9] + red[10] + red[11]) * rq * rk;

    float4 q4 = ((const float4*)q_s)[lane];
    q4.x *= rq; q4.y *= rq; q4.z *= rq; q4.w *= rq;
    float4 k4 = ((const float4*)k_s)[lane];
    k4.x *= rk; k4.y *= rk; k4.z *= rk; k4.w *= rk;

    float*       op = out + (size_t)bh * HKD + wid * 32;
    const float* vr = v_s + wid * 32;

    // ---- 8 batches of 4 rows; prefetch distance 2: batch j+2 issues
    //      right after batch j's dots consume the buffer, so the shuffle
    //      phase always overlaps 4-8 in-flight loads ----
#pragma unroll
    for (int j = 0; j < 8; j++) {
        float4* cur = buf[j & 1];

        float dk0 = dot4(cur[0], k4), dq0 = dot4(cur[0], q4);
        float dk1 = dot4(cur[1], k4), dq1 = dot4(cur[1], q4);
        float dk2 = dot4(cur[2], k4), dq2 = dot4(cur[2], q4);
        float dk3 = dot4(cur[3], k4), dq3 = dot4(cur[3], q4);

        if (j < 6) {
            cur[0] = __ldcs(Sb + ((j + 2) * 4 + 0) * 32);
            cur[1] = __ldcs(Sb + ((j + 2) * 4 + 1) * 32);
            cur[2] = __ldcs(Sb + ((j + 2) * 4 + 2) * 32);
            cur[3] = __ldcs(Sb + ((j + 2) * 4 + 3) * 32);
        }

        dk0 = wredu(dk0); dq0 = wredu(dq0);
        dk1 = wredu(dk1); dq1 = wredu(dq1);
        dk2 = wredu(dk2); dq2 = wredu(dq2);
        dk3 = wredu(dk3); dq3 = wredu(dq3);

        if (lane == 0) {
            const int r = j * 4;
            op[r + 0] = eg * dq0 + beta * (vr[r + 0] - eg * dk0) * kq;
            op[r + 1] = eg * dq1 + beta * (vr[r + 1] - eg * dk1) * kq;
            op[r + 2] = eg * dq2 + beta * (vr[r + 2] - eg * dk2) * kq;
            op[r + 3] = eg * dq3 + beta * (vr[r + 3] - eg * dk3) * kq;
        }
    }
}

extern "C" void kernel_launch(void* const* d_in, const int* in_sizes, int n_in,
                              void* d_out, int out_size)
{
    const float* mixed_qkv  = (const float*)d_in[0];
    const float* bgate      = (const float*)d_in[1];
    const float* agate      = (const float*)d_in[2];
    const float* conv_state = (const float*)d_in[3];
    const float* conv_w     = (const float*)d_in[4];
    const float* ssm        = (const float*)d_in[5];
    const float* alog       = (const float*)d_in[6];
    const float* dt_bias    = (const float*)d_in[7];
    float* out = (float*)d_out;

    const int B = in_sizes[0] / QKVD;
    gdn_decode_kernel<<<B * NVH, 128>>>(mixed_qkv, bgate, agate, conv_state,
                                        conv_w, ssm, alog, dt_bias, out);
}